// round 2
// baseline (speedup 1.0000x reference)
#include <cuda_runtime.h>

#define N_AGENTS 4096
#define TPB 256
#define JPT 16          // 4096 / 256 candidates per thread
#define TOPK 32
#define W2T_LD 132      // padded leading dim for transposed W2 in smem

__global__ __launch_bounds__(TPB)
void controller_kernel(
    const float4* __restrict__ states4,   // [N,4] viewed as float4
    const float*  __restrict__ goals,     // [N,2]
    const float*  __restrict__ W1,  const float* __restrict__ b1,
    const float*  __restrict__ W2,  const float* __restrict__ b2,
    const float*  __restrict__ Wd1, const float* __restrict__ bd1,
    const float*  __restrict__ Wd2, const float* __restrict__ bd2,
    const float*  __restrict__ Wd3, const float* __restrict__ bd3,
    const float*  __restrict__ Wd4, const float* __restrict__ bd4,
    float* __restrict__ out)              // [N,2]
{
    __shared__ __align__(16) float w2t[64 * W2T_LD];   // W2 transposed [c][o], padded
    __shared__ __align__(16) float h1s[64 * 32];       // h1 [c=o1][p]
    __shared__ __align__(16) float xkflat[TOPK * 5];   // xk flat [k][c] == scrambled h[5][32]
    __shared__ __align__(16) float W1s[64 * 5];
    __shared__ float b1s[64];
    __shared__ float masksh[TOPK];
    __shared__ unsigned selsh[TOPK];
    __shared__ unsigned long long warpmin[8];
    __shared__ float featsh[132];
    __shared__ float z1s[64];
    __shared__ float z2s[128];
    __shared__ float z3s[64];
    __shared__ float z4s[4];

    const int tid  = threadIdx.x;
    const int i    = blockIdx.x;
    const int lane = tid & 31;
    const int wid  = tid >> 5;

    const float4 si = states4[i];

    // ---- stage W1/b1 and W2 (transposed) into shared ----
    for (int t = tid; t < 320; t += TPB) W1s[t] = W1[t];
    if (tid < 64) b1s[tid] = b1[tid];
    for (int idx = tid; idx < 8192; idx += TPB) {
        int o = idx >> 6, c = idx & 63;          // idx = o*64 + c (coalesced read)
        w2t[c * W2T_LD + o] = W2[idx];
    }

    // ---- phase A: pairwise planar distances, keys in registers ----
    unsigned long long key[JPT];
    #pragma unroll
    for (int k = 0; k < JPT; k++) {
        int j = tid + k * TPB;
        float4 sj = states4[j];
        float dx = si.x - sj.x;
        float dy = si.y - sj.y;
        float d  = sqrtf(dx * dx + dy * dy + 1e-4f);
        key[k] = (((unsigned long long)__float_as_uint(d)) << 32) | (unsigned)j;
    }
    unsigned removed = 0;
    unsigned long long lm = ~0ull;
    #pragma unroll
    for (int k = 0; k < JPT; k++) lm = (key[k] < lm) ? key[k] : lm;

    // ---- phase B: 32 rounds of block argmin (exact top-k with tie-break) ----
    for (int r = 0; r < TOPK; r++) {
        unsigned long long v = lm;
        #pragma unroll
        for (int off = 16; off; off >>= 1) {
            unsigned long long o = __shfl_xor_sync(0xffffffffu, v, off);
            v = (o < v) ? o : v;
        }
        if (lane == 0) warpmin[wid] = v;
        __syncthreads();
        unsigned long long gm = warpmin[0];
        #pragma unroll
        for (int w = 1; w < 8; w++) {
            unsigned long long t = warpmin[w];
            gm = (t < gm) ? t : gm;
        }
        if (tid == 0) selsh[r] = (unsigned)gm;   // low 32 bits = j
        if (lm == gm) {                          // unique winner (j unique)
            #pragma unroll
            for (int k = 0; k < JPT; k++)
                if (key[k] == gm) removed |= (1u << k);
            lm = ~0ull;
            #pragma unroll
            for (int k = 0; k < JPT; k++) {
                unsigned long long kk = ((removed >> k) & 1u) ? ~0ull : key[k];
                lm = (kk < lm) ? kk : lm;
            }
        }
        __syncthreads();
    }

    // ---- phase C: gather xk rows (flat [k][c]) + obs mask + tail features ----
    if (tid < TOPK) {
        int j = (int)selsh[tid];
        float4 sj = states4[j];
        float dx = si.x - sj.x;
        float dy = si.y - sj.y;
        xkflat[tid * 5 + 0] = dx;
        xkflat[tid * 5 + 1] = dy;
        xkflat[tid * 5 + 2] = si.z - sj.z;
        xkflat[tid * 5 + 3] = si.w - sj.w;
        xkflat[tid * 5 + 4] = (j == i) ? 1.0f : 0.0f;
        masksh[tid] = (sqrtf(dx * dx + dy * dy) < 1.0f) ? 1.0f : 0.0f;
    }
    if (tid == 0) {
        float gx = goals[2 * i], gy = goals[2 * i + 1];
        featsh[128] = si.x - gx;
        featsh[129] = si.y - gy;
        featsh[130] = si.z;
        featsh[131] = si.w;
    }
    __syncthreads();

    // ---- phase D: conv1 5->64  (h[c][p] = xkflat[c*32+p], the raw-reshape view) ----
    for (int idx = tid; idx < 2048; idx += TPB) {
        int o = idx >> 5, p = idx & 31;
        float acc = b1s[o];
        #pragma unroll
        for (int c = 0; c < 5; c++)
            acc = fmaf(W1s[o * 5 + c], xkflat[c * 32 + p], acc);
        h1s[idx] = fmaxf(acc, 0.0f);
    }
    __syncthreads();

    // ---- phase E: conv2 64->128 + masked argmax (4o x 4p register tile) ----
    {
        const int to = tid >> 3;           // o base = to*4   (0..31)
        const int tp = (tid & 7) << 2;     // p base          (0..28)
        float acc[4][4];
        #pragma unroll
        for (int oo = 0; oo < 4; oo++)
            #pragma unroll
            for (int pp = 0; pp < 4; pp++) acc[oo][pp] = 0.0f;

        #pragma unroll 8
        for (int c = 0; c < 64; c++) {
            const float4 w = *reinterpret_cast<const float4*>(&w2t[c * W2T_LD + (to << 2)]);
            const float4 h = *reinterpret_cast<const float4*>(&h1s[(c << 5) + tp]);
            const float ww[4] = {w.x, w.y, w.z, w.w};
            const float hh[4] = {h.x, h.y, h.z, h.w};
            #pragma unroll
            for (int oo = 0; oo < 4; oo++)
                #pragma unroll
                for (int pp = 0; pp < 4; pp++)
                    acc[oo][pp] = fmaf(ww[oo], hh[pp], acc[oo][pp]);
        }

        float mk[4];
        #pragma unroll
        for (int pp = 0; pp < 4; pp++) mk[pp] = masksh[tp + pp];

        #pragma unroll
        for (int oo = 0; oo < 4; oo++) {
            int o = (to << 2) + oo;
            float bb = b2[o];
            float bv = 0.0f;
            int   bp = 0;
            #pragma unroll
            for (int pp = 0; pp < 4; pp++) {
                float v = fmaxf(acc[oo][pp] + bb, 0.0f) * mk[pp];
                if (pp == 0) { bv = v; bp = tp; }
                else if (v > bv) { bv = v; bp = tp + pp; }   // strict > keeps first index
            }
            // combine across the 8 threads sharing this o (first-index tie rule)
            #pragma unroll
            for (int off = 1; off < 8; off <<= 1) {
                float ov = __shfl_xor_sync(0xffffffffu, bv, off);
                int   op = __shfl_xor_sync(0xffffffffu, bp, off);
                if (ov > bv || (ov == bv && op < bp)) { bv = ov; bp = op; }
            }
            if ((tid & 7) == 0) featsh[o] = (float)bp;
        }
    }
    __syncthreads();

    // ---- phase F: MLP 132 -> 64 -> 128 -> 64 -> 4 ----
    for (int o = wid; o < 64; o += 8) {
        float s = 0.0f;
        for (int c = lane; c < 132; c += 32)
            s = fmaf(Wd1[o * 132 + c], featsh[c], s);
        #pragma unroll
        for (int off = 16; off; off >>= 1) s += __shfl_xor_sync(0xffffffffu, s, off);
        if (lane == 0) z1s[o] = fmaxf(s + bd1[o], 0.0f);
    }
    __syncthreads();

    for (int o = wid; o < 128; o += 8) {
        float s = 0.0f;
        #pragma unroll
        for (int c = lane; c < 64; c += 32)
            s = fmaf(Wd2[o * 64 + c], z1s[c], s);
        #pragma unroll
        for (int off = 16; off; off >>= 1) s += __shfl_xor_sync(0xffffffffu, s, off);
        if (lane == 0) z2s[o] = fmaxf(s + bd2[o], 0.0f);
    }
    __syncthreads();

    for (int o = wid; o < 64; o += 8) {
        float s = 0.0f;
        #pragma unroll
        for (int c = lane; c < 128; c += 32)
            s = fmaf(Wd3[o * 128 + c], z2s[c], s);
        #pragma unroll
        for (int off = 16; off; off >>= 1) s += __shfl_xor_sync(0xffffffffu, s, off);
        if (lane == 0) z3s[o] = fmaxf(s + bd3[o], 0.0f);
    }
    __syncthreads();

    if (wid < 4) {
        int o = wid;
        float s = 0.0f;
        #pragma unroll
        for (int c = lane; c < 64; c += 32)
            s = fmaf(Wd4[o * 64 + c], z3s[c], s);
        #pragma unroll
        for (int off = 16; off; off >>= 1) s += __shfl_xor_sync(0xffffffffu, s, off);
        if (lane == 0) z4s[o] = s + bd4[o];
    }
    __syncthreads();

    // ---- phase G: gains + control output ----
    if (tid == 0) {
        float k0 = 2.0f / (1.0f + expf(-z4s[0])) + 0.2f;
        float k1 = 2.0f / (1.0f + expf(-z4s[1])) + 0.2f;
        float k2 = 2.0f / (1.0f + expf(-z4s[2])) + 0.2f;
        float k3 = 2.0f / (1.0f + expf(-z4s[3])) + 0.2f;
        float rx = featsh[128], ry = featsh[129];
        float v2 = featsh[130], v3 = featsh[131];
        out[2 * i + 0] = -(k0 * rx + k1 * v2);
        out[2 * i + 1] = -(k2 * ry + k3 * v3);
    }
}

extern "C" void kernel_launch(void* const* d_in, const int* in_sizes, int n_in,
                              void* d_out, int out_size)
{
    (void)in_sizes; (void)n_in; (void)out_size;
    controller_kernel<<<N_AGENTS, TPB>>>(
        (const float4*)d_in[0],  (const float*)d_in[1],
        (const float*)d_in[2],   (const float*)d_in[3],
        (const float*)d_in[4],   (const float*)d_in[5],
        (const float*)d_in[6],   (const float*)d_in[7],
        (const float*)d_in[8],   (const float*)d_in[9],
        (const float*)d_in[10],  (const float*)d_in[11],
        (const float*)d_in[12],  (const float*)d_in[13],
        (float*)d_out);
}